// round 1
// baseline (speedup 1.0000x reference)
#include <cuda_runtime.h>
#include <math.h>

// ---------------- constants ----------------
#define TL   1024     // T_LEN
#define DM   1024     // DIM
#define DI   2048     // D_INNER
#define DS   16       // D_STATE

// per-scale time lengths: 1024, 512, 256; offsets into packed buffers
// xoff in units of rows*DI ; bcoff in rows*32

// ---------------- scratch (no cudaMalloc allowed) ----------------
__device__ float g_xz   [TL * 4096];          // xz = [x_in | gate]
__device__ float g_xs1  [512 * DI];
__device__ float g_xs2  [256 * DI];
__device__ float g_xc   [(1024 + 512 + 256) * DI];
__device__ float g_dt   [(1024 + 512 + 256) * DI];
__device__ float g_bc   [(1024 + 512 + 256) * 32];
__device__ float g_y    [(1024 + 512 + 256) * DI];
__device__ float g_fused[TL * DI];
__device__ float g_ctx  [TL * DI];
__device__ float g_g1   [TL * 1024];
__device__ float g_pre  [TL * DI];
__device__ float g_yln  [TL * DM];

// ---------------- helpers ----------------
static __device__ __forceinline__ float softplusf(float x) {
    return fmaxf(x, 0.0f) + log1pf(expf(-fabsf(x)));
}

// ---------------- generic SGEMM: C[M,N] = A[M,K] * W[N,K]^T ----------------
enum { EPI_NONE = 0, EPI_SILU = 1, EPI_GATE = 2, EPI_RES = 3 };

template <int EPI>
__global__ __launch_bounds__(256)
void gemm_nt(const float* __restrict__ A, int lda,
             const float* __restrict__ W, int ldw,
             float* __restrict__ C, int ldc, int K,
             const float* __restrict__ aux1, int ld1,
             const float* __restrict__ aux2, int ld2)
{
    __shared__ __align__(16) float As[16][68];
    __shared__ __align__(16) float Ws[16][68];

    const int tid  = threadIdx.x;
    const int tx   = tid & 15;
    const int ty   = tid >> 4;
    const int m0   = blockIdx.y << 6;
    const int n0   = blockIdx.x << 6;
    const int lrow = tid >> 2;         // 0..63
    const int lcol = (tid & 3) << 2;   // 0,4,8,12

    const float* Ap = A + (size_t)(m0 + lrow) * lda + lcol;
    const float* Wp = W + (size_t)(n0 + lrow) * ldw + lcol;

    float acc[4][4];
#pragma unroll
    for (int i = 0; i < 4; i++)
#pragma unroll
        for (int j = 0; j < 4; j++) acc[i][j] = 0.0f;

    for (int k0 = 0; k0 < K; k0 += 16) {
        float4 av = *reinterpret_cast<const float4*>(Ap + k0);
        float4 wv = *reinterpret_cast<const float4*>(Wp + k0);
        __syncthreads();
        As[lcol + 0][lrow] = av.x; As[lcol + 1][lrow] = av.y;
        As[lcol + 2][lrow] = av.z; As[lcol + 3][lrow] = av.w;
        Ws[lcol + 0][lrow] = wv.x; Ws[lcol + 1][lrow] = wv.y;
        Ws[lcol + 2][lrow] = wv.z; Ws[lcol + 3][lrow] = wv.w;
        __syncthreads();
#pragma unroll
        for (int k = 0; k < 16; k++) {
            float4 a = *reinterpret_cast<const float4*>(&As[k][ty << 2]);
            float4 b = *reinterpret_cast<const float4*>(&Ws[k][tx << 2]);
            float ar[4] = {a.x, a.y, a.z, a.w};
            float br[4] = {b.x, b.y, b.z, b.w};
#pragma unroll
            for (int i = 0; i < 4; i++)
#pragma unroll
                for (int j = 0; j < 4; j++)
                    acc[i][j] = fmaf(ar[i], br[j], acc[i][j]);
        }
    }

#pragma unroll
    for (int i = 0; i < 4; i++) {
        int m = m0 + (ty << 2) + i;
        int n = n0 + (tx << 2);
        float4 o4;
        float* op = &o4.x;
#pragma unroll
        for (int j = 0; j < 4; j++) {
            float v = acc[i][j];
            if (EPI == EPI_SILU) {
                v = v / (1.0f + expf(-v));
            } else if (EPI == EPI_GATE) {
                float f = aux1[(size_t)m * ld1 + n + j];
                float g = aux2[(size_t)m * ld2 + n + j];
                v = f * (1.0f / (1.0f + expf(-v))) * (g / (1.0f + expf(-g)));
            } else if (EPI == EPI_RES) {
                v = v + aux1[(size_t)m * ld1 + n + j];
            }
            op[j] = v;
        }
        *reinterpret_cast<float4*>(&C[(size_t)m * ldc + n]) = o4;
    }
}

// ---------------- downsample (avg pool over time) ----------------
__global__ void downsample_kernel(const float* __restrict__ Xin,  // x_in view, row stride 4096
                                  float* __restrict__ out, int T_out, int stride)
{
    int idx = blockIdx.x * blockDim.x + threadIdx.x;
    if (idx >= T_out * DI) return;
    int d = idx & (DI - 1);
    int t = idx >> 11;
    float s = 0.0f;
    for (int r = 0; r < stride; r++)
        s += Xin[(size_t)(t * stride + r) * 4096 + d];
    out[idx] = s * (1.0f / (float)stride);
}

// ---------------- causal depthwise conv (K=4) + silu ----------------
__global__ void conv_silu_kernel(const float* __restrict__ X, int ldx,
                                 const float* __restrict__ cw,   // [DI][4]
                                 const float* __restrict__ cb,   // [DI]
                                 float* __restrict__ xc, int T)
{
    int idx = blockIdx.x * blockDim.x + threadIdx.x;
    if (idx >= T * DI) return;
    int d = idx & (DI - 1);
    int t = idx >> 11;
    const float* w = cw + d * 4;
    float acc = cb[d];
#pragma unroll
    for (int k = 0; k < 4; k++) {
        int tt = t - 3 + k;
        if (tt >= 0) acc = fmaf(X[(size_t)tt * ldx + d], w[k], acc);
    }
    xc[idx] = acc / (1.0f + expf(-acc));   // silu
}

// ---------------- xproj: proj[T,32] = xc[T,DI] @ xw[32,DI]^T ----------------
__global__ __launch_bounds__(256)
void xproj_kernel(const float* __restrict__ xc, const float* __restrict__ xw,
                  float* __restrict__ bc, int T)
{
    int t = blockIdx.x;
    int lane = threadIdx.x & 31;
    int warp = threadIdx.x >> 5;   // 0..7
    const float* row = xc + (size_t)t * DI;
    float p[4] = {0.f, 0.f, 0.f, 0.f};
    for (int d = lane; d < DI; d += 32) {
        float xv = row[d];
#pragma unroll
        for (int q = 0; q < 4; q++) {
            int j = warp + q * 8;
            p[q] = fmaf(xv, xw[(size_t)j * DI + d], p[q]);
        }
    }
#pragma unroll
    for (int q = 0; q < 4; q++) {
#pragma unroll
        for (int o = 16; o > 0; o >>= 1) p[q] += __shfl_xor_sync(0xffffffffu, p[q], o);
        if (lane == 0) bc[t * 32 + warp + q * 8] = p[q];
    }
}

// ---------------- dt = softplus(softplus(B @ dtw^T + dtb)) ----------------
__global__ void dt_kernel(const float* __restrict__ bc, const float* __restrict__ dtw,
                          const float* __restrict__ dtb, float* __restrict__ dt, int T)
{
    int idx = blockIdx.x * blockDim.x + threadIdx.x;
    if (idx >= T * DI) return;
    int d = idx & (DI - 1);
    int t = idx >> 11;
    const float* Brow = bc + t * 32;       // first 16 cols = B_ssm
    const float* wrow = dtw + d * 16;
    float acc = dtb[d];
#pragma unroll
    for (int n = 0; n < DS; n++) acc = fmaf(Brow[n], wrow[n], acc);
    dt[idx] = softplusf(softplusf(acc));
}

// ---------------- SSM scan: warp = 2 channels x 16 states ----------------
// h[t] = max(exp(dt*A),1e-38)*h[t-1] + max(dt*B*xc,1e-38)
// y[t,d] = sum_n C[t,n]*h[t,d,n] + D[d]*xc[t,d]
__global__ __launch_bounds__(256)
void scan_kernel(const float* __restrict__ dt, const float* __restrict__ xc,
                 const float* __restrict__ bc, const float* __restrict__ Dp,
                 float* __restrict__ y, int T)
{
    int lane = threadIdx.x & 31;
    int warp = (blockIdx.x * blockDim.x + threadIdx.x) >> 5;
    int d = warp * 2 + (lane >> 4);
    int n = lane & 15;
    if (d >= DI) return;
    const float A  = -(float)(n + 1);
    const float Dv = Dp[d];
    float h = 0.0f;
    for (int t = 0; t < T; t++) {
        float dtv = dt[(size_t)t * DI + d];
        float xcv = xc[(size_t)t * DI + d];
        float Bv  = bc[t * 32 + n];
        float Cv  = bc[t * 32 + 16 + n];
        float a = __expf(dtv * A);
        a = fmaxf(a, 1e-38f);
        float b = dtv * Bv * xcv;
        b = fmaxf(b, 1e-38f);
        h = fmaf(a, h, b);
        float c = Cv * h;
        c += __shfl_xor_sync(0xffffffffu, c, 8);
        c += __shfl_xor_sync(0xffffffffu, c, 4);
        c += __shfl_xor_sync(0xffffffffu, c, 2);
        c += __shfl_xor_sync(0xffffffffu, c, 1);
        if (n == 0) y[(size_t)t * DI + d] = c + Dv * xcv;
    }
}

// ---------------- fuse: upsample + softmax-weighted sum + ctx ----------------
__global__ void fuse_kernel(const float* __restrict__ y0, const float* __restrict__ y1,
                            const float* __restrict__ y2, const float* __restrict__ sw,
                            float* __restrict__ fused, float* __restrict__ ctx)
{
    int idx = blockIdx.x * blockDim.x + threadIdx.x;
    if (idx >= TL * DI) return;
    int d = idx & (DI - 1);
    int t = idx >> 11;

    float w0 = sw[0], w1 = sw[1], w2 = sw[2];
    float m = fmaxf(w0, fmaxf(w1, w2));
    float e0 = expf(w0 - m), e1 = expf(w1 - m), e2 = expf(w2 - m);
    float inv = 1.0f / (e0 + e1 + e2);

    float o0 = y0[idx];

    float p1 = (t + 0.5f) * 0.5f - 0.5f;
    p1 = fminf(fmaxf(p1, 0.0f), 511.0f);
    int lo1 = (int)floorf(p1);
    int hi1 = min(lo1 + 1, 511);
    float f1 = p1 - (float)lo1;
    float o1 = y1[(size_t)lo1 * DI + d] * (1.0f - f1) + y1[(size_t)hi1 * DI + d] * f1;

    float p2 = (t + 0.5f) * 0.25f - 0.5f;
    p2 = fminf(fmaxf(p2, 0.0f), 255.0f);
    int lo2 = (int)floorf(p2);
    int hi2 = min(lo2 + 1, 255);
    float f2 = p2 - (float)lo2;
    float o2 = y2[(size_t)lo2 * DI + d] * (1.0f - f2) + y2[(size_t)hi2 * DI + d] * f2;

    fused[idx] = (e0 * o0 + e1 * o1 + e2 * o2) * inv;
    ctx[idx]   = (o0 + o1 + o2) * (1.0f / 3.0f);
}

// ---------------- layernorm over last dim (1024) ----------------
__global__ __launch_bounds__(256)
void layernorm_kernel(const float* __restrict__ Y, const float* __restrict__ g,
                      const float* __restrict__ b, float* __restrict__ out)
{
    int t = blockIdx.x;
    int tid = threadIdx.x;
    const float* row = Y + (size_t)t * DM;
    float4 v = *reinterpret_cast<const float4*>(row + tid * 4);
    float s = (v.x + v.y) + (v.z + v.w);
    __shared__ float sh[8];
#pragma unroll
    for (int o = 16; o > 0; o >>= 1) s += __shfl_xor_sync(0xffffffffu, s, o);
    if ((tid & 31) == 0) sh[tid >> 5] = s;
    __syncthreads();
    float tot = 0.0f;
#pragma unroll
    for (int i = 0; i < 8; i++) tot += sh[i];
    float mu = tot * (1.0f / 1024.0f);
    float dx0 = v.x - mu, dx1 = v.y - mu, dx2 = v.z - mu, dx3 = v.w - mu;
    float q = dx0 * dx0 + dx1 * dx1 + dx2 * dx2 + dx3 * dx3;
    __syncthreads();
#pragma unroll
    for (int o = 16; o > 0; o >>= 1) q += __shfl_xor_sync(0xffffffffu, q, o);
    if ((tid & 31) == 0) sh[tid >> 5] = q;
    __syncthreads();
    float qt = 0.0f;
#pragma unroll
    for (int i = 0; i < 8; i++) qt += sh[i];
    float var = qt * (1.0f / 1024.0f);
    float invs = rsqrtf(var + 1e-5f);
    float4 gg = *reinterpret_cast<const float4*>(g + tid * 4);
    float4 bb = *reinterpret_cast<const float4*>(b + tid * 4);
    float4 o4;
    o4.x = dx0 * invs * gg.x + bb.x;
    o4.y = dx1 * invs * gg.y + bb.y;
    o4.z = dx2 * invs * gg.z + bb.z;
    o4.w = dx3 * invs * gg.w + bb.w;
    *reinterpret_cast<float4*>(out + (size_t)t * DM + tid * 4) = o4;
}

// ---------------- launch ----------------
extern "C" void kernel_launch(void* const* d_in, const int* in_sizes, int n_in,
                              void* d_out, int out_size)
{
    (void)in_sizes; (void)n_in; (void)out_size;
    const float* x          = (const float*)d_in[0];
    const float* in_proj_w  = (const float*)d_in[1];
    const float* conv_w     = (const float*)d_in[2];
    const float* conv_b     = (const float*)d_in[3];
    const float* xproj_w    = (const float*)d_in[4];
    const float* dtproj_w   = (const float*)d_in[5];
    const float* dtproj_b   = (const float*)d_in[6];
    const float* D_param    = (const float*)d_in[7];
    const float* sw         = (const float*)d_in[8];
    const float* gate_w1    = (const float*)d_in[9];
    const float* gate_w2    = (const float*)d_in[10];
    const float* out_proj_w = (const float*)d_in[11];
    const float* ln_g       = (const float*)d_in[12];
    const float* ln_b       = (const float*)d_in[13];
    float* out = (float*)d_out;

    float *xz, *xs1, *xs2, *xc, *dt, *bc, *yb, *fused, *ctx, *g1, *pre, *yln;
    cudaGetSymbolAddress((void**)&xz,    g_xz);
    cudaGetSymbolAddress((void**)&xs1,   g_xs1);
    cudaGetSymbolAddress((void**)&xs2,   g_xs2);
    cudaGetSymbolAddress((void**)&xc,    g_xc);
    cudaGetSymbolAddress((void**)&dt,    g_dt);
    cudaGetSymbolAddress((void**)&bc,    g_bc);
    cudaGetSymbolAddress((void**)&yb,    g_y);
    cudaGetSymbolAddress((void**)&fused, g_fused);
    cudaGetSymbolAddress((void**)&ctx,   g_ctx);
    cudaGetSymbolAddress((void**)&g1,    g_g1);
    cudaGetSymbolAddress((void**)&pre,   g_pre);
    cudaGetSymbolAddress((void**)&yln,   g_yln);

    const int Ts[3]    = {1024, 512, 256};
    const int xoff[3]  = {0, 1024 * DI, (1024 + 512) * DI};
    const int bcoff[3] = {0, 1024 * 32, (1024 + 512) * 32};

    // 1) in_proj: xz[1024,4096] = x @ in_proj_w^T
    gemm_nt<EPI_NONE><<<dim3(4096 / 64, 1024 / 64), 256>>>(
        x, 1024, in_proj_w, 1024, xz, 4096, 1024, nullptr, 0, nullptr, 0);

    // 2) downsample x_in (columns [0,2048) of xz, row stride 4096)
    downsample_kernel<<<(512 * DI + 255) / 256, 256>>>(xz, xs1, 512, 2);
    downsample_kernel<<<(256 * DI + 255) / 256, 256>>>(xz, xs2, 256, 4);

    // 3) causal dwconv + silu per scale
    conv_silu_kernel<<<(1024 * DI + 255) / 256, 256>>>(xz, 4096, conv_w,            conv_b,          xc + xoff[0], 1024);
    conv_silu_kernel<<<(512  * DI + 255) / 256, 256>>>(xs1, DI,  conv_w + DI * 4,   conv_b + DI,     xc + xoff[1], 512);
    conv_silu_kernel<<<(256  * DI + 255) / 256, 256>>>(xs2, DI,  conv_w + 2*DI*4,   conv_b + 2*DI,   xc + xoff[2], 256);

    // 4) xproj -> [B_ssm | C_ssm]
    for (int s = 0; s < 3; s++)
        xproj_kernel<<<Ts[s], 256>>>(xc + xoff[s], xproj_w + (size_t)s * 32 * DI, bc + bcoff[s], Ts[s]);

    // 5) dt
    for (int s = 0; s < 3; s++)
        dt_kernel<<<(Ts[s] * DI + 255) / 256, 256>>>(
            bc + bcoff[s], dtproj_w + (size_t)s * DI * DS, dtproj_b + (size_t)s * DI,
            dt + xoff[s], Ts[s]);

    // 6) scan -> y_s
    for (int s = 0; s < 3; s++)
        scan_kernel<<<128, 256>>>(dt + xoff[s], xc + xoff[s], bc + bcoff[s],
                                  D_param + (size_t)s * DI, yb + xoff[s], Ts[s]);

    // 7) fuse (upsample + weighted sum + ctx)
    fuse_kernel<<<(TL * DI + 255) / 256, 256>>>(yb + xoff[0], yb + xoff[1], yb + xoff[2],
                                                sw, fused, ctx);

    // 8) gate path + output projection
    gemm_nt<EPI_SILU><<<dim3(1024 / 64, 1024 / 64), 256>>>(
        ctx, DI, gate_w1, DI, g1, 1024, DI, nullptr, 0, nullptr, 0);
    gemm_nt<EPI_GATE><<<dim3(2048 / 64, 1024 / 64), 256>>>(
        g1, 1024, gate_w2, 1024, pre, DI, 1024, fused, DI, xz + 2048, 4096);
    gemm_nt<EPI_RES><<<dim3(1024 / 64, 1024 / 64), 256>>>(
        pre, DI, out_proj_w, DI, yln, 1024, DI, x, 1024, nullptr, 0);

    // 9) layernorm -> d_out
    layernorm_kernel<<<1024, 256>>>(yln, ln_g, ln_b, out);
}

// round 2
// speedup vs baseline: 1.2338x; 1.2338x over previous
#include <cuda_runtime.h>
#include <math.h>
#include <stdint.h>

// ---------------- constants ----------------
#define TL   1024     // T_LEN
#define DM   1024     // DIM
#define DI   2048     // D_INNER
#define DS   16       // D_STATE

// ---------------- scratch (no cudaMalloc allowed) ----------------
__device__ float g_xz   [TL * 4096];          // xz = [x_in | gate]
__device__ float g_xs1  [512 * DI];
__device__ float g_xs2  [256 * DI];
__device__ float g_xc   [(1024 + 512 + 256) * DI];
__device__ float g_dt   [(1024 + 512 + 256) * DI];
__device__ float g_bc   [(1024 + 512 + 256) * 32];
__device__ float g_y    [(1024 + 512 + 256) * DI];
__device__ float g_fused[TL * DI];
__device__ float g_ctx  [TL * DI];
__device__ float g_g1   [TL * 1024];
__device__ float g_pre  [TL * DI];
__device__ float g_yln  [TL * DM];

// ---------------- helpers ----------------
static __device__ __forceinline__ float softplusf(float x) {
    return fmaxf(x, 0.0f) + log1pf(expf(-fabsf(x)));
}

static __device__ __forceinline__ uint32_t f2tf32(float x) {
    uint32_t u;
    asm("cvt.rna.tf32.f32 %0, %1;" : "=r"(u) : "f"(x));
    return u;
}

static __device__ __forceinline__ void mma_tf32(float* d, const uint32_t* a, const uint32_t* b) {
    asm volatile(
        "mma.sync.aligned.m16n8k8.row.col.f32.tf32.tf32.f32 "
        "{%0,%1,%2,%3}, {%4,%5,%6,%7}, {%8,%9}, {%0,%1,%2,%3};"
        : "+f"(d[0]), "+f"(d[1]), "+f"(d[2]), "+f"(d[3])
        : "r"(a[0]), "r"(a[1]), "r"(a[2]), "r"(a[3]), "r"(b[0]), "r"(b[1]));
}

// ---------------- TF32 tensor-core GEMM: C[M,N] = A[M,K] * W[N,K]^T ----------
// Block tile 128x128, BK=16, 256 threads = 8 warps, warp tile 64x32.
enum { EPI_NONE = 0, EPI_SILU = 1, EPI_GATE = 2, EPI_RES = 3 };

template <int EPI>
__global__ __launch_bounds__(256)
void gemm_tf32(const float* __restrict__ A, int lda,
               const float* __restrict__ W, int ldw,
               float* __restrict__ C, int ldc, int K,
               const float* __restrict__ aux1, int ld1,
               const float* __restrict__ aux2, int ld2)
{
    __shared__ __align__(16) uint32_t As[128][20];   // stride 20: conflict-free frag reads
    __shared__ __align__(16) uint32_t Ws[128][20];

    const int tid  = threadIdx.x;
    const int lane = tid & 31;
    const int wid  = tid >> 5;
    const int m0   = blockIdx.y << 7;
    const int n0   = blockIdx.x << 7;
    const int wm   = (wid >> 2) << 6;   // 0 or 64
    const int wn   = (wid & 3) << 5;    // 0,32,64,96
    const int lrow = tid >> 1;          // 0..127
    const int lcol = (tid & 1) << 3;    // 0 or 8

    const int gid = lane >> 2;          // groupID 0..7
    const int tig = lane & 3;           // thread in group 0..3

    const float* Ap = A + (size_t)(m0 + lrow) * lda + lcol;
    const float* Wp = W + (size_t)(n0 + lrow) * ldw + lcol;

    float acc[4][4][4];
#pragma unroll
    for (int i = 0; i < 4; i++)
#pragma unroll
        for (int j = 0; j < 4; j++)
#pragma unroll
            for (int q = 0; q < 4; q++) acc[i][j][q] = 0.0f;

    for (int k0 = 0; k0 < K; k0 += 16) {
        float4 av0 = *reinterpret_cast<const float4*>(Ap + k0);
        float4 av1 = *reinterpret_cast<const float4*>(Ap + k0 + 4);
        float4 wv0 = *reinterpret_cast<const float4*>(Wp + k0);
        float4 wv1 = *reinterpret_cast<const float4*>(Wp + k0 + 4);

        uint4 at0 = make_uint4(f2tf32(av0.x), f2tf32(av0.y), f2tf32(av0.z), f2tf32(av0.w));
        uint4 at1 = make_uint4(f2tf32(av1.x), f2tf32(av1.y), f2tf32(av1.z), f2tf32(av1.w));
        uint4 wt0 = make_uint4(f2tf32(wv0.x), f2tf32(wv0.y), f2tf32(wv0.z), f2tf32(wv0.w));
        uint4 wt1 = make_uint4(f2tf32(wv1.x), f2tf32(wv1.y), f2tf32(wv1.z), f2tf32(wv1.w));

        __syncthreads();
        *reinterpret_cast<uint4*>(&As[lrow][lcol])     = at0;
        *reinterpret_cast<uint4*>(&As[lrow][lcol + 4]) = at1;
        *reinterpret_cast<uint4*>(&Ws[lrow][lcol])     = wt0;
        *reinterpret_cast<uint4*>(&Ws[lrow][lcol + 4]) = wt1;
        __syncthreads();

#pragma unroll
        for (int kk = 0; kk < 16; kk += 8) {
            uint32_t af[4][4];
            uint32_t bf[4][2];
#pragma unroll
            for (int mt = 0; mt < 4; mt++) {
                int r = wm + (mt << 4) + gid;
                af[mt][0] = As[r][kk + tig];
                af[mt][1] = As[r + 8][kk + tig];
                af[mt][2] = As[r][kk + tig + 4];
                af[mt][3] = As[r + 8][kk + tig + 4];
            }
#pragma unroll
            for (int nt = 0; nt < 4; nt++) {
                int n = wn + (nt << 3) + gid;
                bf[nt][0] = Ws[n][kk + tig];
                bf[nt][1] = Ws[n][kk + tig + 4];
            }
#pragma unroll
            for (int mt = 0; mt < 4; mt++)
#pragma unroll
                for (int nt = 0; nt < 4; nt++)
                    mma_tf32(acc[mt][nt], af[mt], bf[nt]);
        }
    }

    // ---- epilogue ----
#pragma unroll
    for (int mt = 0; mt < 4; mt++) {
#pragma unroll
        for (int nt = 0; nt < 4; nt++) {
            int row0 = m0 + wm + (mt << 4) + gid;
            int col  = n0 + wn + (nt << 3) + (tig << 1);
#pragma unroll
            for (int half = 0; half < 2; half++) {
                int m = row0 + half * 8;
                float v0 = acc[mt][nt][half * 2 + 0];
                float v1 = acc[mt][nt][half * 2 + 1];
                if (EPI == EPI_SILU) {
                    v0 = v0 / (1.0f + expf(-v0));
                    v1 = v1 / (1.0f + expf(-v1));
                } else if (EPI == EPI_GATE) {
                    float f0 = aux1[(size_t)m * ld1 + col];
                    float f1 = aux1[(size_t)m * ld1 + col + 1];
                    float g0 = aux2[(size_t)m * ld2 + col];
                    float g1 = aux2[(size_t)m * ld2 + col + 1];
                    v0 = f0 * (1.0f / (1.0f + expf(-v0))) * (g0 / (1.0f + expf(-g0)));
                    v1 = f1 * (1.0f / (1.0f + expf(-v1))) * (g1 / (1.0f + expf(-g1)));
                } else if (EPI == EPI_RES) {
                    v0 += aux1[(size_t)m * ld1 + col];
                    v1 += aux1[(size_t)m * ld1 + col + 1];
                }
                float2 o2 = make_float2(v0, v1);
                *reinterpret_cast<float2*>(&C[(size_t)m * ldc + col]) = o2;
            }
        }
    }
}

// ---------------- downsample (avg pool over time) ----------------
__global__ void downsample_kernel(const float* __restrict__ Xin,  // row stride 4096
                                  float* __restrict__ out, int T_out, int stride)
{
    int idx = blockIdx.x * blockDim.x + threadIdx.x;
    if (idx >= T_out * DI) return;
    int d = idx & (DI - 1);
    int t = idx >> 11;
    float s = 0.0f;
    for (int r = 0; r < stride; r++)
        s += Xin[(size_t)(t * stride + r) * 4096 + d];
    out[idx] = s * (1.0f / (float)stride);
}

// ---------------- causal depthwise conv (K=4) + silu ----------------
__global__ void conv_silu_kernel(const float* __restrict__ X, int ldx,
                                 const float* __restrict__ cw,   // [DI][4]
                                 const float* __restrict__ cb,   // [DI]
                                 float* __restrict__ xc, int T)
{
    int idx = blockIdx.x * blockDim.x + threadIdx.x;
    if (idx >= T * DI) return;
    int d = idx & (DI - 1);
    int t = idx >> 11;
    const float* w = cw + d * 4;
    float acc = cb[d];
#pragma unroll
    for (int k = 0; k < 4; k++) {
        int tt = t - 3 + k;
        if (tt >= 0) acc = fmaf(X[(size_t)tt * ldx + d], w[k], acc);
    }
    xc[idx] = acc / (1.0f + expf(-acc));   // silu
}

// ---------------- xproj: proj[T,32] = xc[T,DI] @ xw[32,DI]^T ----------------
__global__ __launch_bounds__(256)
void xproj_kernel(const float* __restrict__ xc, const float* __restrict__ xw,
                  float* __restrict__ bc, int T)
{
    int t = blockIdx.x;
    int lane = threadIdx.x & 31;
    int warp = threadIdx.x >> 5;   // 0..7
    const float* row = xc + (size_t)t * DI;
    float p[4] = {0.f, 0.f, 0.f, 0.f};
    for (int d = lane; d < DI; d += 32) {
        float xv = row[d];
#pragma unroll
        for (int q = 0; q < 4; q++) {
            int j = warp + q * 8;
            p[q] = fmaf(xv, xw[(size_t)j * DI + d], p[q]);
        }
    }
#pragma unroll
    for (int q = 0; q < 4; q++) {
#pragma unroll
        for (int o = 16; o > 0; o >>= 1) p[q] += __shfl_xor_sync(0xffffffffu, p[q], o);
        if (lane == 0) bc[t * 32 + warp + q * 8] = p[q];
    }
}

// ---------------- dt = softplus(softplus(B @ dtw^T + dtb)) ----------------
__global__ void dt_kernel(const float* __restrict__ bc, const float* __restrict__ dtw,
                          const float* __restrict__ dtb, float* __restrict__ dt, int T)
{
    int idx = blockIdx.x * blockDim.x + threadIdx.x;
    if (idx >= T * DI) return;
    int d = idx & (DI - 1);
    int t = idx >> 11;
    const float* Brow = bc + t * 32;       // first 16 cols = B_ssm
    const float* wrow = dtw + d * 16;
    float acc = dtb[d];
#pragma unroll
    for (int n = 0; n < DS; n++) acc = fmaf(Brow[n], wrow[n], acc);
    dt[idx] = softplusf(softplusf(acc));
}

// ---------------- SSM scan: warp = 2 channels x 16 states ----------------
__global__ __launch_bounds__(256)
void scan_kernel(const float* __restrict__ dt, const float* __restrict__ xc,
                 const float* __restrict__ bc, const float* __restrict__ Dp,
                 float* __restrict__ y, int T)
{
    int lane = threadIdx.x & 31;
    int warp = (blockIdx.x * blockDim.x + threadIdx.x) >> 5;
    int d = warp * 2 + (lane >> 4);
    int n = lane & 15;
    if (d >= DI) return;
    const float A  = -(float)(n + 1);
    const float Dv = Dp[d];
    float h = 0.0f;
    for (int t = 0; t < T; t++) {
        float dtv = dt[(size_t)t * DI + d];
        float xcv = xc[(size_t)t * DI + d];
        float Bv  = bc[t * 32 + n];
        float Cv  = bc[t * 32 + 16 + n];
        float a = __expf(dtv * A);
        a = fmaxf(a, 1e-38f);
        float b = dtv * Bv * xcv;
        b = fmaxf(b, 1e-38f);
        h = fmaf(a, h, b);
        float c = Cv * h;
        c += __shfl_xor_sync(0xffffffffu, c, 8);
        c += __shfl_xor_sync(0xffffffffu, c, 4);
        c += __shfl_xor_sync(0xffffffffu, c, 2);
        c += __shfl_xor_sync(0xffffffffu, c, 1);
        if (n == 0) y[(size_t)t * DI + d] = c + Dv * xcv;
    }
}

// ---------------- fuse: upsample + softmax-weighted sum + ctx ----------------
__global__ void fuse_kernel(const float* __restrict__ y0, const float* __restrict__ y1,
                            const float* __restrict__ y2, const float* __restrict__ sw,
                            float* __restrict__ fused, float* __restrict__ ctx)
{
    int idx = blockIdx.x * blockDim.x + threadIdx.x;
    if (idx >= TL * DI) return;
    int d = idx & (DI - 1);
    int t = idx >> 11;

    float w0 = sw[0], w1 = sw[1], w2 = sw[2];
    float m = fmaxf(w0, fmaxf(w1, w2));
    float e0 = expf(w0 - m), e1 = expf(w1 - m), e2 = expf(w2 - m);
    float inv = 1.0f / (e0 + e1 + e2);

    float o0 = y0[idx];

    float p1 = (t + 0.5f) * 0.5f - 0.5f;
    p1 = fminf(fmaxf(p1, 0.0f), 511.0f);
    int lo1 = (int)floorf(p1);
    int hi1 = min(lo1 + 1, 511);
    float f1 = p1 - (float)lo1;
    float o1 = y1[(size_t)lo1 * DI + d] * (1.0f - f1) + y1[(size_t)hi1 * DI + d] * f1;

    float p2 = (t + 0.5f) * 0.25f - 0.5f;
    p2 = fminf(fmaxf(p2, 0.0f), 255.0f);
    int lo2 = (int)floorf(p2);
    int hi2 = min(lo2 + 1, 255);
    float f2 = p2 - (float)lo2;
    float o2 = y2[(size_t)lo2 * DI + d] * (1.0f - f2) + y2[(size_t)hi2 * DI + d] * f2;

    fused[idx] = (e0 * o0 + e1 * o1 + e2 * o2) * inv;
    ctx[idx]   = (o0 + o1 + o2) * (1.0f / 3.0f);
}

// ---------------- layernorm over last dim (1024) ----------------
__global__ __launch_bounds__(256)
void layernorm_kernel(const float* __restrict__ Y, const float* __restrict__ g,
                      const float* __restrict__ b, float* __restrict__ out)
{
    int t = blockIdx.x;
    int tid = threadIdx.x;
    const float* row = Y + (size_t)t * DM;
    float4 v = *reinterpret_cast<const float4*>(row + tid * 4);
    float s = (v.x + v.y) + (v.z + v.w);
    __shared__ float sh[8];
#pragma unroll
    for (int o = 16; o > 0; o >>= 1) s += __shfl_xor_sync(0xffffffffu, s, o);
    if ((tid & 31) == 0) sh[tid >> 5] = s;
    __syncthreads();
    float tot = 0.0f;
#pragma unroll
    for (int i = 0; i < 8; i++) tot += sh[i];
    float mu = tot * (1.0f / 1024.0f);
    float dx0 = v.x - mu, dx1 = v.y - mu, dx2 = v.z - mu, dx3 = v.w - mu;
    float q = dx0 * dx0 + dx1 * dx1 + dx2 * dx2 + dx3 * dx3;
    __syncthreads();
#pragma unroll
    for (int o = 16; o > 0; o >>= 1) q += __shfl_xor_sync(0xffffffffu, q, o);
    if ((tid & 31) == 0) sh[tid >> 5] = q;
    __syncthreads();
    float qt = 0.0f;
#pragma unroll
    for (int i = 0; i < 8; i++) qt += sh[i];
    float var = qt * (1.0f / 1024.0f);
    float invs = rsqrtf(var + 1e-5f);
    float4 gg = *reinterpret_cast<const float4*>(g + tid * 4);
    float4 bb = *reinterpret_cast<const float4*>(b + tid * 4);
    float4 o4;
    o4.x = dx0 * invs * gg.x + bb.x;
    o4.y = dx1 * invs * gg.y + bb.y;
    o4.z = dx2 * invs * gg.z + bb.z;
    o4.w = dx3 * invs * gg.w + bb.w;
    *reinterpret_cast<float4*>(out + (size_t)t * DM + tid * 4) = o4;
}

// ---------------- launch ----------------
extern "C" void kernel_launch(void* const* d_in, const int* in_sizes, int n_in,
                              void* d_out, int out_size)
{
    (void)in_sizes; (void)n_in; (void)out_size;
    const float* x          = (const float*)d_in[0];
    const float* in_proj_w  = (const float*)d_in[1];
    const float* conv_w     = (const float*)d_in[2];
    const float* conv_b     = (const float*)d_in[3];
    const float* xproj_w    = (const float*)d_in[4];
    const float* dtproj_w   = (const float*)d_in[5];
    const float* dtproj_b   = (const float*)d_in[6];
    const float* D_param    = (const float*)d_in[7];
    const float* sw         = (const float*)d_in[8];
    const float* gate_w1    = (const float*)d_in[9];
    const float* gate_w2    = (const float*)d_in[10];
    const float* out_proj_w = (const float*)d_in[11];
    const float* ln_g       = (const float*)d_in[12];
    const float* ln_b       = (const float*)d_in[13];
    float* out = (float*)d_out;

    float *xz, *xs1, *xs2, *xc, *dt, *bc, *yb, *fused, *ctx, *g1, *pre, *yln;
    cudaGetSymbolAddress((void**)&xz,    g_xz);
    cudaGetSymbolAddress((void**)&xs1,   g_xs1);
    cudaGetSymbolAddress((void**)&xs2,   g_xs2);
    cudaGetSymbolAddress((void**)&xc,    g_xc);
    cudaGetSymbolAddress((void**)&dt,    g_dt);
    cudaGetSymbolAddress((void**)&bc,    g_bc);
    cudaGetSymbolAddress((void**)&yb,    g_y);
    cudaGetSymbolAddress((void**)&fused, g_fused);
    cudaGetSymbolAddress((void**)&ctx,   g_ctx);
    cudaGetSymbolAddress((void**)&g1,    g_g1);
    cudaGetSymbolAddress((void**)&pre,   g_pre);
    cudaGetSymbolAddress((void**)&yln,   g_yln);

    const int Ts[3]    = {1024, 512, 256};
    const int xoff[3]  = {0, 1024 * DI, (1024 + 512) * DI};
    const int bcoff[3] = {0, 1024 * 32, (1024 + 512) * 32};

    // 1) in_proj: xz[1024,4096] = x @ in_proj_w^T
    gemm_tf32<EPI_NONE><<<dim3(4096 / 128, 1024 / 128), 256>>>(
        x, 1024, in_proj_w, 1024, xz, 4096, 1024, nullptr, 0, nullptr, 0);

    // 2) downsample x_in (columns [0,2048) of xz, row stride 4096)
    downsample_kernel<<<(512 * DI + 255) / 256, 256>>>(xz, xs1, 512, 2);
    downsample_kernel<<<(256 * DI + 255) / 256, 256>>>(xz, xs2, 256, 4);

    // 3) causal dwconv + silu per scale
    conv_silu_kernel<<<(1024 * DI + 255) / 256, 256>>>(xz, 4096, conv_w,          conv_b,        xc + xoff[0], 1024);
    conv_silu_kernel<<<(512  * DI + 255) / 256, 256>>>(xs1, DI,  conv_w + DI * 4, conv_b + DI,   xc + xoff[1], 512);
    conv_silu_kernel<<<(256  * DI + 255) / 256, 256>>>(xs2, DI,  conv_w + 2*DI*4, conv_b + 2*DI, xc + xoff[2], 256);

    // 4) xproj -> [B_ssm | C_ssm]
    for (int s = 0; s < 3; s++)
        xproj_kernel<<<Ts[s], 256>>>(xc + xoff[s], xproj_w + (size_t)s * 32 * DI, bc + bcoff[s], Ts[s]);

    // 5) dt
    for (int s = 0; s < 3; s++)
        dt_kernel<<<(Ts[s] * DI + 255) / 256, 256>>>(
            bc + bcoff[s], dtproj_w + (size_t)s * DI * DS, dtproj_b + (size_t)s * DI,
            dt + xoff[s], Ts[s]);

    // 6) scan -> y_s
    for (int s = 0; s < 3; s++)
        scan_kernel<<<128, 256>>>(dt + xoff[s], xc + xoff[s], bc + bcoff[s],
                                  D_param + (size_t)s * DI, yb + xoff[s], Ts[s]);

    // 7) fuse (upsample + weighted sum + ctx)
    fuse_kernel<<<(TL * DI + 255) / 256, 256>>>(yb + xoff[0], yb + xoff[1], yb + xoff[2],
                                                sw, fused, ctx);

    // 8) gate path + output projection
    gemm_tf32<EPI_SILU><<<dim3(1024 / 128, 1024 / 128), 256>>>(
        ctx, DI, gate_w1, DI, g1, 1024, DI, nullptr, 0, nullptr, 0);
    gemm_tf32<EPI_GATE><<<dim3(2048 / 128, 1024 / 128), 256>>>(
        g1, 1024, gate_w2, 1024, pre, DI, 1024, fused, DI, xz + 2048, 4096);
    gemm_tf32<EPI_RES><<<dim3(1024 / 128, 1024 / 128), 256>>>(
        pre, DI, out_proj_w, DI, yln, 1024, DI, x, 1024, nullptr, 0);

    // 9) layernorm -> d_out
    layernorm_kernel<<<1024, 256>>>(yln, ln_g, ln_b, out);
}

// round 4
// speedup vs baseline: 1.5802x; 1.2808x over previous
#include <cuda_runtime.h>
#include <math.h>
#include <stdint.h>

// ---------------- constants ----------------
#define TL   1024     // T_LEN
#define DM   1024     // DIM
#define DI   2048     // D_INNER
#define DS   16       // D_STATE

// ---------------- scratch (no cudaMalloc allowed) ----------------
__device__ float g_xz   [TL * 4096];          // xz = [x_in | gate]
__device__ float g_xs1  [512 * DI];
__device__ float g_xs2  [256 * DI];
__device__ float g_xc   [(1024 + 512 + 256) * DI];
__device__ float g_dt   [(1024 + 512 + 256) * DI];
__device__ float g_bc   [(1024 + 512 + 256) * 32];
__device__ float g_y    [(1024 + 512 + 256) * DI];
__device__ float g_fused[TL * DI];
__device__ float g_ctx  [TL * DI];
__device__ float g_g1   [TL * 1024];
__device__ float g_pre  [TL * DI];
__device__ float g_yln  [TL * DM];

// ---------------- helpers ----------------
static __device__ __forceinline__ float softplusf(float x) {
    return fmaxf(x, 0.0f) + log1pf(expf(-fabsf(x)));
}

static __device__ __forceinline__ void cp_async16(void* smem_dst, const void* gsrc) {
    uint32_t s = (uint32_t)__cvta_generic_to_shared(smem_dst);
    asm volatile("cp.async.cg.shared.global [%0], [%1], 16;\n" :: "r"(s), "l"(gsrc));
}
static __device__ __forceinline__ void cp_commit() {
    asm volatile("cp.async.commit_group;\n");
}
static __device__ __forceinline__ void cp_waitall() {
    asm volatile("cp.async.wait_all;\n" ::: "memory");
}

static __device__ __forceinline__ void mma_tf32(float* d, const uint32_t* a, const uint32_t* b) {
    asm volatile(
        "mma.sync.aligned.m16n8k8.row.col.f32.tf32.tf32.f32 "
        "{%0,%1,%2,%3}, {%4,%5,%6,%7}, {%8,%9}, {%0,%1,%2,%3};"
        : "+f"(d[0]), "+f"(d[1]), "+f"(d[2]), "+f"(d[3])
        : "r"(a[0]), "r"(a[1]), "r"(a[2]), "r"(a[3]), "r"(b[0]), "r"(b[1]));
}

// ---------------- TF32 tensor-core GEMM: C[M,N] = A[M,K] * W[N,K]^T ----------
// Block tile BM x 128, BK=16, 256 threads = 8 warps (2 x 4), warp tile (BM/2) x 32.
// 2-stage cp.async pipeline. fp32 raw bits fed to tf32 mma (HW truncation).
enum { EPI_NONE = 0, EPI_SILU = 1, EPI_GATE = 2, EPI_RES = 3 };

template <int EPI, int BM>
__global__ __launch_bounds__(256)
void gemm_tc(const float* __restrict__ A, int lda,
             const float* __restrict__ W, int ldw,
             float* __restrict__ C, int ldc, int K,
             const float* __restrict__ aux1, int ld1,
             const float* __restrict__ aux2, int ld2)
{
    constexpr int MT = BM / 32;               // 4 (BM=128) or 2 (BM=64)
    __shared__ __align__(16) float As[2][BM][20];
    __shared__ __align__(16) float Ws[2][128][20];

    const int tid  = threadIdx.x;
    const int lane = tid & 31;
    const int wid  = tid >> 5;
    const int m0   = blockIdx.y * BM;
    const int n0   = blockIdx.x << 7;
    const int wm   = (wid >> 2) * (BM / 2);
    const int wn   = (wid & 3) << 5;
    const int gid  = lane >> 2;
    const int tig  = lane & 3;

    // copy mapping
    const int a_row = (BM == 128) ? (tid >> 1) : (tid >> 2);
    const int a_col = (BM == 128) ? ((tid & 1) << 3) : ((tid & 3) << 2);
    const int w_row = tid >> 1;
    const int w_col = (tid & 1) << 3;

    const float* Ap = A + (size_t)(m0 + a_row) * lda + a_col;
    const float* Wp = W + (size_t)(n0 + w_row) * ldw + w_col;

    float acc[MT][4][4];
#pragma unroll
    for (int i = 0; i < MT; i++)
#pragma unroll
        for (int j = 0; j < 4; j++)
#pragma unroll
            for (int q = 0; q < 4; q++) acc[i][j][q] = 0.0f;

    const int KT = K >> 4;

    // prologue: stage 0 <- tile 0
    {
        cp_async16(&As[0][a_row][a_col], Ap);
        if (BM == 128) cp_async16(&As[0][a_row][a_col + 4], Ap + 4);
        cp_async16(&Ws[0][w_row][w_col], Wp);
        cp_async16(&Ws[0][w_row][w_col + 4], Wp + 4);
        cp_commit();
    }

    for (int kt = 0; kt < KT; kt++) {
        const int st = kt & 1;
        cp_waitall();
        __syncthreads();

        if (kt + 1 < KT) {
            const int ns = st ^ 1;
            const int k0 = (kt + 1) << 4;
            cp_async16(&As[ns][a_row][a_col], Ap + k0);
            if (BM == 128) cp_async16(&As[ns][a_row][a_col + 4], Ap + k0 + 4);
            cp_async16(&Ws[ns][w_row][w_col], Wp + k0);
            cp_async16(&Ws[ns][w_row][w_col + 4], Wp + k0 + 4);
            cp_commit();
        }

#pragma unroll
        for (int kk = 0; kk < 16; kk += 8) {
            uint32_t af[MT][4];
            uint32_t bf[4][2];
#pragma unroll
            for (int mt = 0; mt < MT; mt++) {
                int r = wm + (mt << 4) + gid;
                af[mt][0] = __float_as_uint(As[st][r][kk + tig]);
                af[mt][1] = __float_as_uint(As[st][r + 8][kk + tig]);
                af[mt][2] = __float_as_uint(As[st][r][kk + tig + 4]);
                af[mt][3] = __float_as_uint(As[st][r + 8][kk + tig + 4]);
            }
#pragma unroll
            for (int nt = 0; nt < 4; nt++) {
                int n = wn + (nt << 3) + gid;
                bf[nt][0] = __float_as_uint(Ws[st][n][kk + tig]);
                bf[nt][1] = __float_as_uint(Ws[st][n][kk + tig + 4]);
            }
#pragma unroll
            for (int mt = 0; mt < MT; mt++)
#pragma unroll
                for (int nt = 0; nt < 4; nt++)
                    mma_tf32(acc[mt][nt], af[mt], bf[nt]);
        }
        __syncthreads();
    }

    // ---- epilogue ----
#pragma unroll
    for (int mt = 0; mt < MT; mt++) {
#pragma unroll
        for (int nt = 0; nt < 4; nt++) {
            int row0 = m0 + wm + (mt << 4) + gid;
            int col  = n0 + wn + (nt << 3) + (tig << 1);
#pragma unroll
            for (int half = 0; half < 2; half++) {
                int m = row0 + half * 8;
                float v0 = acc[mt][nt][half * 2 + 0];
                float v1 = acc[mt][nt][half * 2 + 1];
                if (EPI == EPI_SILU) {
                    v0 = v0 / (1.0f + expf(-v0));
                    v1 = v1 / (1.0f + expf(-v1));
                } else if (EPI == EPI_GATE) {
                    float f0 = aux1[(size_t)m * ld1 + col];
                    float f1 = aux1[(size_t)m * ld1 + col + 1];
                    float g0 = aux2[(size_t)m * ld2 + col];
                    float g1 = aux2[(size_t)m * ld2 + col + 1];
                    v0 = f0 * (1.0f / (1.0f + expf(-v0))) * (g0 / (1.0f + expf(-g0)));
                    v1 = f1 * (1.0f / (1.0f + expf(-v1))) * (g1 / (1.0f + expf(-g1)));
                } else if (EPI == EPI_RES) {
                    v0 += aux1[(size_t)m * ld1 + col];
                    v1 += aux1[(size_t)m * ld1 + col + 1];
                }
                *reinterpret_cast<float2*>(&C[(size_t)m * ldc + col]) = make_float2(v0, v1);
            }
        }
    }
}

// ---------------- downsample (avg pool over time) ----------------
__global__ void downsample_kernel(const float* __restrict__ Xin,  // row stride 4096
                                  float* __restrict__ out, int T_out, int stride)
{
    int idx = blockIdx.x * blockDim.x + threadIdx.x;
    if (idx >= T_out * DI) return;
    int d = idx & (DI - 1);
    int t = idx >> 11;
    float s = 0.0f;
    for (int r = 0; r < stride; r++)
        s += Xin[(size_t)(t * stride + r) * 4096 + d];
    out[idx] = s * (1.0f / (float)stride);
}

// ---------------- causal depthwise conv (K=4) + silu ----------------
__global__ void conv_silu_kernel(const float* __restrict__ X, int ldx,
                                 const float* __restrict__ cw,   // [DI][4]
                                 const float* __restrict__ cb,   // [DI]
                                 float* __restrict__ xc, int T)
{
    int idx = blockIdx.x * blockDim.x + threadIdx.x;
    if (idx >= T * DI) return;
    int d = idx & (DI - 1);
    int t = idx >> 11;
    const float* w = cw + d * 4;
    float acc = cb[d];
#pragma unroll
    for (int k = 0; k < 4; k++) {
        int tt = t - 3 + k;
        if (tt >= 0) acc = fmaf(X[(size_t)tt * ldx + d], w[k], acc);
    }
    xc[idx] = acc / (1.0f + expf(-acc));   // silu
}

// ---------------- xproj: proj[T,32] = xc[T,DI] @ xw[32,DI]^T ----------------
__global__ __launch_bounds__(256)
void xproj_kernel(const float* __restrict__ xc, const float* __restrict__ xw,
                  float* __restrict__ bc, int T)
{
    int t = blockIdx.x;
    int lane = threadIdx.x & 31;
    int warp = threadIdx.x >> 5;   // 0..7
    const float* row = xc + (size_t)t * DI;
    float p[4] = {0.f, 0.f, 0.f, 0.f};
    for (int d = lane; d < DI; d += 32) {
        float xv = row[d];
#pragma unroll
        for (int q = 0; q < 4; q++) {
            int j = warp + q * 8;
            p[q] = fmaf(xv, xw[(size_t)j * DI + d], p[q]);
        }
    }
#pragma unroll
    for (int q = 0; q < 4; q++) {
#pragma unroll
        for (int o = 16; o > 0; o >>= 1) p[q] += __shfl_xor_sync(0xffffffffu, p[q], o);
        if (lane == 0) bc[t * 32 + warp + q * 8] = p[q];
    }
}

// ---------------- dt = softplus(softplus(B @ dtw^T + dtb)) ----------------
__global__ void dt_kernel(const float* __restrict__ bc, const float* __restrict__ dtw,
                          const float* __restrict__ dtb, float* __restrict__ dt, int T)
{
    int idx = blockIdx.x * blockDim.x + threadIdx.x;
    if (idx >= T * DI) return;
    int d = idx & (DI - 1);
    int t = idx >> 11;
    const float* Brow = bc + t * 32;       // first 16 cols = B_ssm
    const float* wrow = dtw + d * 16;
    float acc = dtb[d];
#pragma unroll
    for (int n = 0; n < DS; n++) acc = fmaf(Brow[n], wrow[n], acc);
    dt[idx] = softplusf(softplusf(acc));
}

// ---------------- SSM scan (all 3 scales in one launch, 1-iter prefetch) ----
// warp = 2 channels x 16 states; 1024 warps per scale; 3072 warps total.
__global__ __launch_bounds__(256)
void scan_all_kernel(const float* __restrict__ dtb_, const float* __restrict__ xcb_,
                     const float* __restrict__ bcb_, const float* __restrict__ Dp_,
                     float* __restrict__ yb_)
{
    int gw   = (blockIdx.x * 256 + threadIdx.x) >> 5;   // 0..3071
    int s    = gw >> 10;                                 // scale 0..2
    int w    = gw & 1023;
    int lane = threadIdx.x & 31;
    int d    = w * 2 + (lane >> 4);
    int n    = lane & 15;
    int T    = 1024 >> s;

    const int xo  = (s == 0) ? 0 : (s == 1 ? 1024 * DI : 1536 * DI);
    const int bco = (s == 0) ? 0 : (s == 1 ? 1024 * 32 : 1536 * 32);

    const float* dt = dtb_ + xo;
    const float* xc = xcb_ + xo;
    const float* bc = bcb_ + bco;
    float*       y  = yb_ + xo;

    const float A  = -(float)(n + 1);
    const float Dv = Dp_[s * DI + d];

    float h = 0.0f;
    float dtv = dt[d];
    float xcv = xc[d];
    float Bv  = bc[n];
    float Cv  = bc[16 + n];

    for (int t = 0; t < T; t++) {
        // prefetch next iteration (predicated off on last iter)
        float dtn = 0.f, xcn = 0.f, Bn = 0.f, Cn = 0.f;
        if (t + 1 < T) {
            dtn = dt[(size_t)(t + 1) * DI + d];
            xcn = xc[(size_t)(t + 1) * DI + d];
            Bn  = bc[(t + 1) * 32 + n];
            Cn  = bc[(t + 1) * 32 + 16 + n];
        }
        float a = __expf(dtv * A);
        a = fmaxf(a, 1e-38f);
        float b = dtv * Bv * xcv;
        b = fmaxf(b, 1e-38f);
        h = fmaf(a, h, b);
        float c = Cv * h;
        c += __shfl_xor_sync(0xffffffffu, c, 8);
        c += __shfl_xor_sync(0xffffffffu, c, 4);
        c += __shfl_xor_sync(0xffffffffu, c, 2);
        c += __shfl_xor_sync(0xffffffffu, c, 1);
        if (n == 0) y[(size_t)t * DI + d] = c + Dv * xcv;
        dtv = dtn; xcv = xcn; Bv = Bn; Cv = Cn;
    }
}

// ---------------- fuse: upsample + softmax-weighted sum + ctx ----------------
__global__ void fuse_kernel(const float* __restrict__ y0, const float* __restrict__ y1,
                            const float* __restrict__ y2, const float* __restrict__ sw,
                            float* __restrict__ fused, float* __restrict__ ctx)
{
    int idx = blockIdx.x * blockDim.x + threadIdx.x;
    if (idx >= TL * DI) return;
    int d = idx & (DI - 1);
    int t = idx >> 11;

    float w0 = sw[0], w1 = sw[1], w2 = sw[2];
    float m = fmaxf(w0, fmaxf(w1, w2));
    float e0 = expf(w0 - m), e1 = expf(w1 - m), e2 = expf(w2 - m);
    float inv = 1.0f / (e0 + e1 + e2);

    float o0 = y0[idx];

    float p1 = (t + 0.5f) * 0.5f - 0.5f;
    p1 = fminf(fmaxf(p1, 0.0f), 511.0f);
    int lo1 = (int)floorf(p1);
    int hi1 = min(lo1 + 1, 511);
    float f1 = p1 - (float)lo1;
    float o1 = y1[(size_t)lo1 * DI + d] * (1.0f - f1) + y1[(size_t)hi1 * DI + d] * f1;

    float p2 = (t + 0.5f) * 0.25f - 0.5f;
    p2 = fminf(fmaxf(p2, 0.0f), 255.0f);
    int lo2 = (int)floorf(p2);
    int hi2 = min(lo2 + 1, 255);
    float f2 = p2 - (float)lo2;
    float o2 = y2[(size_t)lo2 * DI + d] * (1.0f - f2) + y2[(size_t)hi2 * DI + d] * f2;

    fused[idx] = (e0 * o0 + e1 * o1 + e2 * o2) * inv;
    ctx[idx]   = (o0 + o1 + o2) * (1.0f / 3.0f);
}

// ---------------- layernorm over last dim (1024) ----------------
__global__ __launch_bounds__(256)
void layernorm_kernel(const float* __restrict__ Y, const float* __restrict__ g,
                      const float* __restrict__ b, float* __restrict__ out)
{
    int t = blockIdx.x;
    int tid = threadIdx.x;
    const float* row = Y + (size_t)t * DM;
    float4 v = *reinterpret_cast<const float4*>(row + tid * 4);
    float s = (v.x + v.y) + (v.z + v.w);
    __shared__ float sh[8];
#pragma unroll
    for (int o = 16; o > 0; o >>= 1) s += __shfl_xor_sync(0xffffffffu, s, o);
    if ((tid & 31) == 0) sh[tid >> 5] = s;
    __syncthreads();
    float tot = 0.0f;
#pragma unroll
    for (int i = 0; i < 8; i++) tot += sh[i];
    float mu = tot * (1.0f / 1024.0f);
    float dx0 = v.x - mu, dx1 = v.y - mu, dx2 = v.z - mu, dx3 = v.w - mu;
    float q = dx0 * dx0 + dx1 * dx1 + dx2 * dx2 + dx3 * dx3;
    __syncthreads();
#pragma unroll
    for (int o = 16; o > 0; o >>= 1) q += __shfl_xor_sync(0xffffffffu, q, o);
    if ((tid & 31) == 0) sh[tid >> 5] = q;
    __syncthreads();
    float qt = 0.0f;
#pragma unroll
    for (int i = 0; i < 8; i++) qt += sh[i];
    float var = qt * (1.0f / 1024.0f);
    float invs = rsqrtf(var + 1e-5f);
    float4 gg = *reinterpret_cast<const float4*>(g + tid * 4);
    float4 bb = *reinterpret_cast<const float4*>(b + tid * 4);
    float4 o4;
    o4.x = dx0 * invs * gg.x + bb.x;
    o4.y = dx1 * invs * gg.y + bb.y;
    o4.z = dx2 * invs * gg.z + bb.z;
    o4.w = dx3 * invs * gg.w + bb.w;
    *reinterpret_cast<float4*>(out + (size_t)t * DM + tid * 4) = o4;
}

// ---------------- launch ----------------
extern "C" void kernel_launch(void* const* d_in, const int* in_sizes, int n_in,
                              void* d_out, int out_size)
{
    (void)in_sizes; (void)n_in; (void)out_size;
    const float* x          = (const float*)d_in[0];
    const float* in_proj_w  = (const float*)d_in[1];
    const float* conv_w     = (const float*)d_in[2];
    const float* conv_b     = (const float*)d_in[3];
    const float* xproj_w    = (const float*)d_in[4];
    const float* dtproj_w   = (const float*)d_in[5];
    const float* dtproj_b   = (const float*)d_in[6];
    const float* D_param    = (const float*)d_in[7];
    const float* sw         = (const float*)d_in[8];
    const float* gate_w1    = (const float*)d_in[9];
    const float* gate_w2    = (const float*)d_in[10];
    const float* out_proj_w = (const float*)d_in[11];
    const float* ln_g       = (const float*)d_in[12];
    const float* ln_b       = (const float*)d_in[13];
    float* out = (float*)d_out;

    float *xz, *xs1, *xs2, *xc, *dt, *bc, *yb, *fused, *ctx, *g1, *pre, *yln;
    cudaGetSymbolAddress((void**)&xz,    g_xz);
    cudaGetSymbolAddress((void**)&xs1,   g_xs1);
    cudaGetSymbolAddress((void**)&xs2,   g_xs2);
    cudaGetSymbolAddress((void**)&xc,    g_xc);
    cudaGetSymbolAddress((void**)&dt,    g_dt);
    cudaGetSymbolAddress((void**)&bc,    g_bc);
    cudaGetSymbolAddress((void**)&yb,    g_y);
    cudaGetSymbolAddress((void**)&fused, g_fused);
    cudaGetSymbolAddress((void**)&ctx,   g_ctx);
    cudaGetSymbolAddress((void**)&g1,    g_g1);
    cudaGetSymbolAddress((void**)&pre,   g_pre);
    cudaGetSymbolAddress((void**)&yln,   g_yln);

    const int Ts[3]    = {1024, 512, 256};
    const int xoff[3]  = {0, 1024 * DI, (1024 + 512) * DI};
    const int bcoff[3] = {0, 1024 * 32, (1024 + 512) * 32};

    // 1) in_proj: xz[1024,4096] = x @ in_proj_w^T
    gemm_tc<EPI_NONE, 128><<<dim3(4096 / 128, 1024 / 128), 256>>>(
        x, 1024, in_proj_w, 1024, xz, 4096, 1024, nullptr, 0, nullptr, 0);

    // 2) downsample x_in (columns [0,2048) of xz, row stride 4096)
    downsample_kernel<<<(512 * DI + 255) / 256, 256>>>(xz, xs1, 512, 2);
    downsample_kernel<<<(256 * DI + 255) / 256, 256>>>(xz, xs2, 256, 4);

    // 3) causal dwconv + silu per scale
    conv_silu_kernel<<<(1024 * DI + 255) / 256, 256>>>(xz, 4096, conv_w,          conv_b,        xc + xoff[0], 1024);
    conv_silu_kernel<<<(512  * DI + 255) / 256, 256>>>(xs1, DI,  conv_w + DI * 4, conv_b + DI,   xc + xoff[1], 512);
    conv_silu_kernel<<<(256  * DI + 255) / 256, 256>>>(xs2, DI,  conv_w + 2*DI*4, conv_b + 2*DI, xc + xoff[2], 256);

    // 4) xproj -> [B_ssm | C_ssm]
    for (int s = 0; s < 3; s++)
        xproj_kernel<<<Ts[s], 256>>>(xc + xoff[s], xproj_w + (size_t)s * 32 * DI, bc + bcoff[s], Ts[s]);

    // 5) dt
    for (int s = 0; s < 3; s++)
        dt_kernel<<<(Ts[s] * DI + 255) / 256, 256>>>(
            bc + bcoff[s], dtproj_w + (size_t)s * DI * DS, dtproj_b + (size_t)s * DI,
            dt + xoff[s], Ts[s]);

    // 6) scan (all scales, one launch)
    scan_all_kernel<<<384, 256>>>(dt, xc, bc, D_param, yb);

    // 7) fuse (upsample + weighted sum + ctx)
    fuse_kernel<<<(TL * DI + 255) / 256, 256>>>(yb + xoff[0], yb + xoff[1], yb + xoff[2],
                                                sw, fused, ctx);

    // 8) gate path + output projection (BM=64 tiles for occupancy)
    gemm_tc<EPI_SILU, 64><<<dim3(1024 / 128, 1024 / 64), 256>>>(
        ctx, DI, gate_w1, DI, g1, 1024, DI, nullptr, 0, nullptr, 0);
    gemm_tc<EPI_GATE, 64><<<dim3(2048 / 128, 1024 / 64), 256>>>(
        g1, 1024, gate_w2, 1024, pre, DI, 1024, fused, DI, xz + 2048, 4096);
    gemm_tc<EPI_RES, 64><<<dim3(1024 / 128, 1024 / 64), 256>>>(
        pre, DI, out_proj_w, DI, yln, 1024, DI, x, 1024, nullptr, 0);

    // 9) layernorm -> d_out
    layernorm_kernel<<<1024, 256>>>(yln, ln_g, ln_b, out);
}

// round 5
// speedup vs baseline: 1.8772x; 1.1879x over previous
#include <cuda_runtime.h>
#include <math.h>
#include <stdint.h>

// ---------------- constants ----------------
#define TL   1024     // T_LEN
#define DM   1024     // DIM
#define DI   2048     // D_INNER
#define DS   16       // D_STATE
#define TROWS (1024 + 512 + 256)   // packed time rows across 3 scales

// ---------------- scratch (no cudaMalloc allowed) ----------------
__device__ float g_xz   [TL * 4096];          // xz = [x_in | gate]
__device__ float g_xs1  [512 * DI];
__device__ float g_xs2  [256 * DI];
__device__ float g_xc   [TROWS * DI];
__device__ float g_dt   [TROWS * DI];
__device__ float g_bc   [TROWS * 32];
__device__ float g_y    [TROWS * DI];
__device__ float g_fused[TL * DI];
__device__ float g_ctx  [TL * DI];
__device__ float g_g1   [TL * 1024];
__device__ float g_pre  [TL * DI];
__device__ float g_yln  [TL * DM];

// ---------------- helpers ----------------
static __device__ __forceinline__ float softplusf(float x) {
    return fmaxf(x, 0.0f) + log1pf(expf(-fabsf(x)));
}

static __device__ __forceinline__ void cp_async16(void* smem_dst, const void* gsrc) {
    uint32_t s = (uint32_t)__cvta_generic_to_shared(smem_dst);
    asm volatile("cp.async.cg.shared.global [%0], [%1], 16;\n" :: "r"(s), "l"(gsrc));
}
static __device__ __forceinline__ void cp_commit() {
    asm volatile("cp.async.commit_group;\n");
}
static __device__ __forceinline__ void cp_wait1() {
    asm volatile("cp.async.wait_group 1;\n" ::: "memory");
}

static __device__ __forceinline__ void mma_tf32(float* d, const uint32_t* a, const uint32_t* b) {
    asm volatile(
        "mma.sync.aligned.m16n8k8.row.col.f32.tf32.tf32.f32 "
        "{%0,%1,%2,%3}, {%4,%5,%6,%7}, {%8,%9}, {%0,%1,%2,%3};"
        : "+f"(d[0]), "+f"(d[1]), "+f"(d[2]), "+f"(d[3])
        : "r"(a[0]), "r"(a[1]), "r"(a[2]), "r"(a[3]), "r"(b[0]), "r"(b[1]));
}

// ---------------- TF32 tensor-core GEMM: C[M,N] = A[M,K] * W[N,K]^T ----------
// Block tile BM x 128, BK=32, 3-stage cp.async ring, 256 threads = 8 warps,
// warp tile (BM/2) x 32. fp32 raw bits fed to tf32 mma (HW truncation).
enum { EPI_NONE = 0, EPI_SILU = 1, EPI_GATE = 2, EPI_RES = 3 };

#define SKS 36   // smem row stride in floats (32 + 4 pad)

template <int EPI, int BM>
__global__ __launch_bounds__(256)
void gemm_tc(const float* __restrict__ A, int lda,
             const float* __restrict__ W, int ldw,
             float* __restrict__ C, int ldc, int K,
             const float* __restrict__ aux1, int ld1,
             const float* __restrict__ aux2, int ld2)
{
    constexpr int MT = BM / 32;               // 4 (BM=128) or 2 (BM=64)
    constexpr int NA4 = BM * 8 / 256;         // float4 copies per thread for A
    extern __shared__ __align__(16) float smem[];
    float* Asm = smem;                        // [3][BM][SKS]
    float* Wsm = smem + 3 * BM * SKS;         // [3][128][SKS]

    const int tid  = threadIdx.x;
    const int lane = tid & 31;
    const int wid  = tid >> 5;
    const int m0   = blockIdx.y * BM;
    const int n0   = blockIdx.x << 7;
    const int wm   = (wid >> 2) * (BM / 2);
    const int wn   = (wid & 3) << 5;
    const int gid  = lane >> 2;
    const int tig  = lane & 3;

    float acc[MT][4][4];
#pragma unroll
    for (int i = 0; i < MT; i++)
#pragma unroll
        for (int j = 0; j < 4; j++)
#pragma unroll
            for (int q = 0; q < 4; q++) acc[i][j][q] = 0.0f;

    const int KT = K >> 5;   // K/32 tiles

    // issue copy of tile kt into stage st
    auto issue = [&](int kt, int st) {
        const float* Ag = A + (size_t)m0 * lda + kt * 32;
        const float* Wg = W + (size_t)n0 * ldw + kt * 32;
        float* As = Asm + st * BM * SKS;
        float* Ws = Wsm + st * 128 * SKS;
#pragma unroll
        for (int i = 0; i < NA4; i++) {
            int idx4 = tid + i * 256;
            int row = idx4 >> 3;
            int col = (idx4 & 7) << 2;
            cp_async16(&As[row * SKS + col], Ag + (size_t)row * lda + col);
        }
#pragma unroll
        for (int i = 0; i < 4; i++) {
            int idx4 = tid + i * 256;
            int row = idx4 >> 3;
            int col = (idx4 & 7) << 2;
            cp_async16(&Ws[row * SKS + col], Wg + (size_t)row * ldw + col);
        }
    };

    // prologue: tiles 0,1 into stages 0,1
    issue(0, 0); cp_commit();
    issue(1, 1); cp_commit();

    for (int kt = 0; kt < KT; kt++) {
        const int st = kt % 3;
        cp_wait1();            // tile kt resident (tile kt+1 may still fly)
        __syncthreads();       // all warps past previous tile's reads + see data

        if (kt + 2 < KT) issue(kt + 2, (kt + 2) % 3);
        cp_commit();           // commit every iter (possibly empty) for group math

        const float* As = Asm + st * BM * SKS;
        const float* Ws = Wsm + st * 128 * SKS;

#pragma unroll
        for (int kk = 0; kk < 32; kk += 8) {
            uint32_t af[MT][4];
            uint32_t bf[4][2];
#pragma unroll
            for (int mt = 0; mt < MT; mt++) {
                int r = wm + (mt << 4) + gid;
                af[mt][0] = __float_as_uint(As[r * SKS + kk + tig]);
                af[mt][1] = __float_as_uint(As[(r + 8) * SKS + kk + tig]);
                af[mt][2] = __float_as_uint(As[r * SKS + kk + tig + 4]);
                af[mt][3] = __float_as_uint(As[(r + 8) * SKS + kk + tig + 4]);
            }
#pragma unroll
            for (int nt = 0; nt < 4; nt++) {
                int n = wn + (nt << 3) + gid;
                bf[nt][0] = __float_as_uint(Ws[n * SKS + kk + tig]);
                bf[nt][1] = __float_as_uint(Ws[n * SKS + kk + tig + 4]);
            }
#pragma unroll
            for (int mt = 0; mt < MT; mt++)
#pragma unroll
                for (int nt = 0; nt < 4; nt++)
                    mma_tf32(acc[mt][nt], af[mt], bf[nt]);
        }
    }

    // ---- epilogue ----
#pragma unroll
    for (int mt = 0; mt < MT; mt++) {
#pragma unroll
        for (int nt = 0; nt < 4; nt++) {
            int row0 = m0 + wm + (mt << 4) + gid;
            int col  = n0 + wn + (nt << 3) + (tig << 1);
#pragma unroll
            for (int half = 0; half < 2; half++) {
                int m = row0 + half * 8;
                float v0 = acc[mt][nt][half * 2 + 0];
                float v1 = acc[mt][nt][half * 2 + 1];
                if (EPI == EPI_SILU) {
                    v0 = v0 / (1.0f + expf(-v0));
                    v1 = v1 / (1.0f + expf(-v1));
                } else if (EPI == EPI_GATE) {
                    float f0 = aux1[(size_t)m * ld1 + col];
                    float f1 = aux1[(size_t)m * ld1 + col + 1];
                    float g0 = aux2[(size_t)m * ld2 + col];
                    float g1 = aux2[(size_t)m * ld2 + col + 1];
                    v0 = f0 * (1.0f / (1.0f + expf(-v0))) * (g0 / (1.0f + expf(-g0)));
                    v1 = f1 * (1.0f / (1.0f + expf(-v1))) * (g1 / (1.0f + expf(-g1)));
                } else if (EPI == EPI_RES) {
                    v0 += aux1[(size_t)m * ld1 + col];
                    v1 += aux1[(size_t)m * ld1 + col + 1];
                }
                *reinterpret_cast<float2*>(&C[(size_t)m * ldc + col]) = make_float2(v0, v1);
            }
        }
    }
}

// ---------------- downsample both scales in one launch ----------------
__global__ void downsample_all_kernel(const float* __restrict__ Xin,  // row stride 4096
                                      float* __restrict__ xs1, float* __restrict__ xs2)
{
    int idx = blockIdx.x * blockDim.x + threadIdx.x;   // over (512+256)*2048
    if (idx >= (512 + 256) * DI) return;
    int d = idx & (DI - 1);
    int r = idx >> 11;
    if (r < 512) {
        float s = Xin[(size_t)(r * 2) * 4096 + d] + Xin[(size_t)(r * 2 + 1) * 4096 + d];
        xs1[r * DI + d] = s * 0.5f;
    } else {
        int t = r - 512;
        float s = 0.0f;
#pragma unroll
        for (int q = 0; q < 4; q++) s += Xin[(size_t)(t * 4 + q) * 4096 + d];
        xs2[t * DI + d] = s * 0.25f;
    }
}

// ---------------- causal depthwise conv (K=4) + silu, all scales ----------
__global__ void conv_all_kernel(const float* __restrict__ xz,
                                const float* __restrict__ xs1,
                                const float* __restrict__ xs2,
                                const float* __restrict__ cw,   // [3][DI][4]
                                const float* __restrict__ cb,   // [3][DI]
                                float* __restrict__ xc)
{
    int idx = blockIdx.x * blockDim.x + threadIdx.x;   // over 1792*2048
    if (idx >= TROWS * DI) return;
    int d = idx & (DI - 1);
    int r = idx >> 11;

    int s, t;
    const float* X; int ldx;
    if (r < 1024)      { s = 0; t = r;        X = xz;  ldx = 4096; }
    else if (r < 1536) { s = 1; t = r - 1024; X = xs1; ldx = DI;   }
    else               { s = 2; t = r - 1536; X = xs2; ldx = DI;   }

    const float* w = cw + (s * DI + d) * 4;
    float acc = cb[s * DI + d];
#pragma unroll
    for (int k = 0; k < 4; k++) {
        int tt = t - 3 + k;
        if (tt >= 0) acc = fmaf(X[(size_t)tt * ldx + d], w[k], acc);
    }
    xc[idx] = acc / (1.0f + expf(-acc));   // silu
}

// ---------------- xproj: proj[r,32] = xc[r,DI] @ xw_s[32,DI]^T -------------
__global__ __launch_bounds__(256)
void xproj_all_kernel(const float* __restrict__ xc, const float* __restrict__ xproj_w,
                      float* __restrict__ bc)
{
    int r = blockIdx.x;                    // 0..1791
    int s = (r < 1024) ? 0 : (r < 1536 ? 1 : 2);
    const float* xw = xproj_w + (size_t)s * 32 * DI;
    int lane = threadIdx.x & 31;
    int warp = threadIdx.x >> 5;   // 0..7
    const float* row = xc + (size_t)r * DI;
    float p[4] = {0.f, 0.f, 0.f, 0.f};
    for (int d = lane; d < DI; d += 32) {
        float xv = row[d];
#pragma unroll
        for (int q = 0; q < 4; q++) {
            int j = warp + q * 8;
            p[q] = fmaf(xv, xw[(size_t)j * DI + d], p[q]);
        }
    }
#pragma unroll
    for (int q = 0; q < 4; q++) {
#pragma unroll
        for (int o = 16; o > 0; o >>= 1) p[q] += __shfl_xor_sync(0xffffffffu, p[q], o);
        if (lane == 0) bc[r * 32 + warp + q * 8] = p[q];
    }
}

// ---------------- dt = softplus(softplus(B @ dtw^T + dtb)), all scales ----
__global__ void dt_all_kernel(const float* __restrict__ bc, const float* __restrict__ dtproj_w,
                              const float* __restrict__ dtproj_b, float* __restrict__ dt)
{
    int idx = blockIdx.x * blockDim.x + threadIdx.x;
    if (idx >= TROWS * DI) return;
    int d = idx & (DI - 1);
    int r = idx >> 11;
    int s = (r < 1024) ? 0 : (r < 1536 ? 1 : 2);
    const float* Brow = bc + r * 32;
    const float* wrow = dtproj_w + ((size_t)s * DI + d) * 16;
    float acc = dtproj_b[s * DI + d];
#pragma unroll
    for (int n = 0; n < DS; n++) acc = fmaf(Brow[n], wrow[n], acc);
    dt[idx] = softplusf(softplusf(acc));
}

// ---------------- SSM scan (all 3 scales in one launch, 1-iter prefetch) ----
__global__ __launch_bounds__(256)
void scan_all_kernel(const float* __restrict__ dtb_, const float* __restrict__ xcb_,
                     const float* __restrict__ bcb_, const float* __restrict__ Dp_,
                     float* __restrict__ yb_)
{
    int gw   = (blockIdx.x * 256 + threadIdx.x) >> 5;   // 0..3071
    int s    = gw >> 10;                                 // scale 0..2
    int w    = gw & 1023;
    int lane = threadIdx.x & 31;
    int d    = w * 2 + (lane >> 4);
    int n    = lane & 15;
    int T    = 1024 >> s;

    const int xo  = (s == 0) ? 0 : (s == 1 ? 1024 * DI : 1536 * DI);
    const int bco = (s == 0) ? 0 : (s == 1 ? 1024 * 32 : 1536 * 32);

    const float* dt = dtb_ + xo;
    const float* xc = xcb_ + xo;
    const float* bc = bcb_ + bco;
    float*       y  = yb_ + xo;

    const float A  = -(float)(n + 1);
    const float Dv = Dp_[s * DI + d];

    float h = 0.0f;
    float dtv = dt[d];
    float xcv = xc[d];
    float Bv  = bc[n];
    float Cv  = bc[16 + n];

    for (int t = 0; t < T; t++) {
        float dtn = 0.f, xcn = 0.f, Bn = 0.f, Cn = 0.f;
        if (t + 1 < T) {
            dtn = dt[(size_t)(t + 1) * DI + d];
            xcn = xc[(size_t)(t + 1) * DI + d];
            Bn  = bc[(t + 1) * 32 + n];
            Cn  = bc[(t + 1) * 32 + 16 + n];
        }
        float a = __expf(dtv * A);
        a = fmaxf(a, 1e-38f);
        float b = dtv * Bv * xcv;
        b = fmaxf(b, 1e-38f);
        h = fmaf(a, h, b);
        float c = Cv * h;
        c += __shfl_xor_sync(0xffffffffu, c, 8);
        c += __shfl_xor_sync(0xffffffffu, c, 4);
        c += __shfl_xor_sync(0xffffffffu, c, 2);
        c += __shfl_xor_sync(0xffffffffu, c, 1);
        if (n == 0) y[(size_t)t * DI + d] = c + Dv * xcv;
        dtv = dtn; xcv = xcn; Bv = Bn; Cv = Cn;
    }
}

// ---------------- fuse: upsample + softmax-weighted sum + ctx ----------------
__global__ void fuse_kernel(const float* __restrict__ y0, const float* __restrict__ y1,
                            const float* __restrict__ y2, const float* __restrict__ sw,
                            float* __restrict__ fused, float* __restrict__ ctx)
{
    int idx = blockIdx.x * blockDim.x + threadIdx.x;
    if (idx >= TL * DI) return;
    int d = idx & (DI - 1);
    int t = idx >> 11;

    float w0 = sw[0], w1 = sw[1], w2 = sw[2];
    float m = fmaxf(w0, fmaxf(w1, w2));
    float e0 = expf(w0 - m), e1 = expf(w1 - m), e2 = expf(w2 - m);
    float inv = 1.0f / (e0 + e1 + e2);

    float o0 = y0[idx];

    float p1 = (t + 0.5f) * 0.5f - 0.5f;
    p1 = fminf(fmaxf(p1, 0.0f), 511.0f);
    int lo1 = (int)floorf(p1);
    int hi1 = min(lo1 + 1, 511);
    float f1 = p1 - (float)lo1;
    float o1 = y1[(size_t)lo1 * DI + d] * (1.0f - f1) + y1[(size_t)hi1 * DI + d] * f1;

    float p2 = (t + 0.5f) * 0.25f - 0.5f;
    p2 = fminf(fmaxf(p2, 0.0f), 255.0f);
    int lo2 = (int)floorf(p2);
    int hi2 = min(lo2 + 1, 255);
    float f2 = p2 - (float)lo2;
    float o2 = y2[(size_t)lo2 * DI + d] * (1.0f - f2) + y2[(size_t)hi2 * DI + d] * f2;

    fused[idx] = (e0 * o0 + e1 * o1 + e2 * o2) * inv;
    ctx[idx]   = (o0 + o1 + o2) * (1.0f / 3.0f);
}

// ---------------- layernorm over last dim (1024) ----------------
__global__ __launch_bounds__(256)
void layernorm_kernel(const float* __restrict__ Y, const float* __restrict__ g,
                      const float* __restrict__ b, float* __restrict__ out)
{
    int t = blockIdx.x;
    int tid = threadIdx.x;
    const float* row = Y + (size_t)t * DM;
    float4 v = *reinterpret_cast<const float4*>(row + tid * 4);
    float s = (v.x + v.y) + (v.z + v.w);
    __shared__ float sh[8];
#pragma unroll
    for (int o = 16; o > 0; o >>= 1) s += __shfl_xor_sync(0xffffffffu, s, o);
    if ((tid & 31) == 0) sh[tid >> 5] = s;
    __syncthreads();
    float tot = 0.0f;
#pragma unroll
    for (int i = 0; i < 8; i++) tot += sh[i];
    float mu = tot * (1.0f / 1024.0f);
    float dx0 = v.x - mu, dx1 = v.y - mu, dx2 = v.z - mu, dx3 = v.w - mu;
    float q = dx0 * dx0 + dx1 * dx1 + dx2 * dx2 + dx3 * dx3;
    __syncthreads();
#pragma unroll
    for (int o = 16; o > 0; o >>= 1) q += __shfl_xor_sync(0xffffffffu, q, o);
    if ((tid & 31) == 0) sh[tid >> 5] = q;
    __syncthreads();
    float qt = 0.0f;
#pragma unroll
    for (int i = 0; i < 8; i++) qt += sh[i];
    float var = qt * (1.0f / 1024.0f);
    float invs = rsqrtf(var + 1e-5f);
    float4 gg = *reinterpret_cast<const float4*>(g + tid * 4);
    float4 bb = *reinterpret_cast<const float4*>(b + tid * 4);
    float4 o4;
    o4.x = dx0 * invs * gg.x + bb.x;
    o4.y = dx1 * invs * gg.y + bb.y;
    o4.z = dx2 * invs * gg.z + bb.z;
    o4.w = dx3 * invs * gg.w + bb.w;
    *reinterpret_cast<float4*>(out + (size_t)t * DM + tid * 4) = o4;
}

// ---------------- launch ----------------
extern "C" void kernel_launch(void* const* d_in, const int* in_sizes, int n_in,
                              void* d_out, int out_size)
{
    (void)in_sizes; (void)n_in; (void)out_size;
    const float* x          = (const float*)d_in[0];
    const float* in_proj_w  = (const float*)d_in[1];
    const float* conv_w     = (const float*)d_in[2];
    const float* conv_b     = (const float*)d_in[3];
    const float* xproj_w    = (const float*)d_in[4];
    const float* dtproj_w   = (const float*)d_in[5];
    const float* dtproj_b   = (const float*)d_in[6];
    const float* D_param    = (const float*)d_in[7];
    const float* sw         = (const float*)d_in[8];
    const float* gate_w1    = (const float*)d_in[9];
    const float* gate_w2    = (const float*)d_in[10];
    const float* out_proj_w = (const float*)d_in[11];
    const float* ln_g       = (const float*)d_in[12];
    const float* ln_b       = (const float*)d_in[13];
    float* out = (float*)d_out;

    float *xz, *xs1, *xs2, *xc, *dt, *bc, *yb, *fused, *ctx, *g1, *pre, *yln;
    cudaGetSymbolAddress((void**)&xz,    g_xz);
    cudaGetSymbolAddress((void**)&xs1,   g_xs1);
    cudaGetSymbolAddress((void**)&xs2,   g_xs2);
    cudaGetSymbolAddress((void**)&xc,    g_xc);
    cudaGetSymbolAddress((void**)&dt,    g_dt);
    cudaGetSymbolAddress((void**)&bc,    g_bc);
    cudaGetSymbolAddress((void**)&yb,    g_y);
    cudaGetSymbolAddress((void**)&fused, g_fused);
    cudaGetSymbolAddress((void**)&ctx,   g_ctx);
    cudaGetSymbolAddress((void**)&g1,    g_g1);
    cudaGetSymbolAddress((void**)&pre,   g_pre);
    cudaGetSymbolAddress((void**)&yln,   g_yln);

    const int smem128 = 3 * (128 + 128) * SKS * 4;   // 110592 B
    const int smem64  = 3 * (64 + 128) * SKS * 4;    //  82944 B
    static bool attr_done = false;
    if (!attr_done) {
        cudaFuncSetAttribute(gemm_tc<EPI_NONE, 128>, cudaFuncAttributeMaxDynamicSharedMemorySize, smem128);
        cudaFuncSetAttribute(gemm_tc<EPI_SILU, 64>,  cudaFuncAttributeMaxDynamicSharedMemorySize, smem64);
        cudaFuncSetAttribute(gemm_tc<EPI_GATE, 64>,  cudaFuncAttributeMaxDynamicSharedMemorySize, smem64);
        cudaFuncSetAttribute(gemm_tc<EPI_RES, 64>,   cudaFuncAttributeMaxDynamicSharedMemorySize, smem64);
        attr_done = true;
    }

    // 1) in_proj: xz[1024,4096] = x @ in_proj_w^T
    gemm_tc<EPI_NONE, 128><<<dim3(4096 / 128, 1024 / 128), 256, smem128>>>(
        x, 1024, in_proj_w, 1024, xz, 4096, 1024, nullptr, 0, nullptr, 0);

    // 2) downsample (both scales)
    downsample_all_kernel<<<((512 + 256) * DI + 255) / 256, 256>>>(xz, xs1, xs2);

    // 3) causal dwconv + silu (all scales)
    conv_all_kernel<<<(TROWS * DI + 255) / 256, 256>>>(xz, xs1, xs2, conv_w, conv_b, xc);

    // 4) xproj (all scales)
    xproj_all_kernel<<<TROWS, 256>>>(xc, xproj_w, bc);

    // 5) dt (all scales)
    dt_all_kernel<<<(TROWS * DI + 255) / 256, 256>>>(bc, dtproj_w, dtproj_b, dt);

    // 6) scan (all scales)
    scan_all_kernel<<<384, 256>>>(dt, xc, bc, D_param, yb);

    // 7) fuse (upsample + weighted sum + ctx)
    fuse_kernel<<<(TL * DI + 255) / 256, 256>>>(yb, yb + 1024 * DI, yb + 1536 * DI,
                                                sw, fused, ctx);

    // 8) gate path + output projection
    gemm_tc<EPI_SILU, 64><<<dim3(1024 / 128, 1024 / 64), 256, smem64>>>(
        ctx, DI, gate_w1, DI, g1, 1024, DI, nullptr, 0, nullptr, 0);
    gemm_tc<EPI_GATE, 64><<<dim3(2048 / 128, 1024 / 64), 256, smem64>>>(
        g1, 1024, gate_w2, 1024, pre, DI, 1024, fused, DI, xz + 2048, 4096);
    gemm_tc<EPI_RES, 64><<<dim3(1024 / 128, 1024 / 64), 256, smem64>>>(
        pre, DI, out_proj_w, DI, yln, 1024, DI, x, 1024, nullptr, 0);

    // 9) layernorm -> d_out
    layernorm_kernel<<<1024, 256>>>(yln, ln_g, ln_b, out);
}